// round 10
// baseline (speedup 1.0000x reference)
#include <cuda_runtime.h>
#include <cuda_bf16.h>

#define Bn 32
#define Nn 8192
#define Gn 256
#define Kn 32
#define CH 1024
#define FULLMASK 0xFFFFFFFFu

#define FPS_SMEM (Nn * 3 * (int)sizeof(float))   // 96 KB point stage

// ---------------------------------------------------------------------------
// Kernel 1: farthest point sampling. One block per batch, 1024 threads,
// 8 points/thread in registers + full point cloud staged in shared.
// Per iter: sub-square distance (reference bit-exact), warp redux max,
// claimant u64 atomicMax (dist, ~idx) -> global argmax with first-index
// tie-break, center coords re-read from shared by index. 2 barriers/iter.
// ---------------------------------------------------------------------------
__global__ __launch_bounds__(1024, 1) void fps_kernel(const float* __restrict__ xyz,
                                                      float* __restrict__ centers)
{
    extern __shared__ float shp[];               // Nn*3 floats
    __shared__ unsigned long long s_best[2];

    const int b   = blockIdx.x;
    const int tid = threadIdx.x;
    const float* xb = xyz + (size_t)b * Nn * 3;

    // stage full cloud: 6144 float4 = 96 KB (byte-identical packed float3)
    {
        const float4* src4 = (const float4*)xb;
        float4* dst4 = (float4*)shp;
        for (int i = tid; i < Nn * 3 / 4; i += 1024) dst4[i] = src4[i];
    }
    if (tid < 2) s_best[tid] = 0ull;
    __syncthreads();

    // private 8 points from shared (tid*96 bytes, 16B aligned)
    float px[8], py[8], pz[8], mind[8];
    {
        float c[24];
        const float4* s4 = (const float4*)(shp + tid * 24);
#pragma unroll
        for (int q = 0; q < 6; q++) {
            float4 v = s4[q];
            c[4 * q + 0] = v.x; c[4 * q + 1] = v.y;
            c[4 * q + 2] = v.z; c[4 * q + 3] = v.w;
        }
#pragma unroll
        for (int i = 0; i < 8; i++) {
            px[i] = c[3 * i + 0];
            py[i] = c[3 * i + 1];
            pz[i] = c[3 * i + 2];
            mind[i] = __int_as_float(0x7f800000);  // +inf
        }
    }

    int cur = 0;
    for (int g = 0; g < Gn; g++) {
        const int p = g & 1;
        // broadcast center coords from shared
        float cx = shp[3 * cur + 0];
        float cy = shp[3 * cur + 1];
        float cz = shp[3 * cur + 2];
        if (tid == 0) {
            float* cp = centers + ((size_t)b * Gn + g) * 3;
            cp[0] = cx; cp[1] = cy; cp[2] = cz;
        }

        float vm = 0.0f;
#pragma unroll
        for (int i = 0; i < 8; i++) {
            // EXACT reference arithmetic: sub then square
            float dx = px[i] - cx, dy = py[i] - cy, dz = pz[i] - cz;
            float d  = dx * dx + dy * dy + dz * dz;
            float m  = fminf(mind[i], d);
            mind[i]  = m;
            vm = fmaxf(vm, m);
        }
        // distances >= 0 -> bit compare == float compare
        unsigned vb   = __float_as_uint(vm);
        unsigned wmax = __reduce_max_sync(FULLMASK, vb);
        if (vb == wmax) {
            int j = -1;
#pragma unroll
            for (int i = 7; i >= 0; i--)
                if (__float_as_uint(mind[i]) == vb) j = i;
            unsigned long long pk =
                ((unsigned long long)vb << 32) |
                (unsigned)(Nn - 1 - (tid * 8 + j));   // larger == smaller idx
            atomicMax(&s_best[p], pk);
        }
        __syncthreads();                              // all claims landed
        cur = Nn - 1 - (int)(unsigned)(s_best[p] & 0xFFFFFFFFull);
        if (tid == 0) s_best[1 - p] = 0ull;           // reset slot for g+1
        __syncthreads();                              // reset visible
    }
}

// ---------------------------------------------------------------------------
// Kernel 2: exact ordered top-32 per group. One warp per group, slots kept
// sorted ascending across lanes by (valbits, idx); lane 31 always holds tau.
// float4-padded shared points (1 LDS.128/pt). rank == lane.
// ---------------------------------------------------------------------------
__global__ __launch_bounds__(256, 8) void knn_kernel(const float* __restrict__ xyz,
                                                     const float* __restrict__ centers,
                                                     float* __restrict__ patch)
{
    __shared__ float4 spts[CH];  // 16 KB chunk, padded float4

    const int b     = blockIdx.x >> 5;        // 32 blocks per batch
    const int gbase = (blockIdx.x & 31) * 8;
    const int wid   = threadIdx.x >> 5;
    const int lane  = threadIdx.x & 31;
    const int g     = gbase + wid;

    const float* cptr = centers + ((size_t)b * Gn + g) * 3;
    float cx = cptr[0], cy = cptr[1], cz = cptr[2];

    // slot: packed (distbits<<32)|idx, sorted ascending by lane
    unsigned long long slot =
        ((unsigned long long)0x7f800000u << 32) | 0xFFFFFFFFull;
    unsigned taub = 0x7f800000u;  // +inf bits

    for (int c = 0; c < Nn / CH; c++) {
        __syncthreads();
        for (int p = threadIdx.x; p < CH; p += 256) {
            const float* s = xyz + ((size_t)b * Nn + c * CH + p) * 3;
            spts[p] = make_float4(s[0], s[1], s[2], 0.0f);
        }
        __syncthreads();

        for (int s = 0; s < CH / 32; s++) {
            float4 v = spts[s * 32 + lane];
            // EXACT reference arithmetic
            float dx = cx - v.x, dy = cy - v.y, dz = cz - v.z;
            float key = dx * dx + dy * dy + dz * dz;
            unsigned kb = __float_as_uint(key);
            unsigned gi = (unsigned)(c * CH + s * 32 + lane);

            // bit compare == float compare for non-negative floats
            unsigned act = __ballot_sync(FULLMASK, kb < taub);
            while (act) {
                int src = __ffs(act) - 1;
                act &= act - 1;
                unsigned ckb = __shfl_sync(FULLMASK, kb, src);
                unsigned cgi = __shfl_sync(FULLMASK, gi, src);
                if (ckb >= taub) continue;  // uniform: tau dropped below it
                unsigned long long cpk =
                    ((unsigned long long)ckb << 32) | cgi;
                bool gtp = slot > cpk;
                unsigned bal = __ballot_sync(FULLMASK, gtp);
                int pos = __ffs(bal) - 1;  // always >= 0: lane31 slot > cpk
                unsigned long long up = __shfl_up_sync(FULLMASK, slot, 1);
                unsigned long long ns = gtp ? up : slot;
                if (lane == pos) ns = cpk;
                slot = ns;
                taub = __shfl_sync(FULLMASK, (unsigned)(slot >> 32), 31);
            }
        }
    }

    // slots sorted: rank == lane
    unsigned sidx = (unsigned)(slot & 0xFFFFFFFFull);
    const float* pp = xyz + ((size_t)b * Nn + sidx) * 3;
    float* outp = patch + (((size_t)(b * Gn + g)) * Kn + lane) * 3;
    outp[0] = pp[0] - cx;
    outp[1] = pp[1] - cy;
    outp[2] = pp[2] - cz;
}

// ---------------------------------------------------------------------------
extern "C" void kernel_launch(void* const* d_in, const int* in_sizes, int n_in,
                              void* d_out, int out_size)
{
    (void)in_sizes; (void)n_in; (void)out_size;
    const float* xyz = (const float*)d_in[0];
    float* out     = (float*)d_out;
    float* patch   = out;                             // (B, G, K, 3)
    float* centers = out + (size_t)Bn * Gn * Kn * 3;  // (B, G, 3)

    cudaFuncSetAttribute(fps_kernel,
                         cudaFuncAttributeMaxDynamicSharedMemorySize, FPS_SMEM);

    fps_kernel<<<Bn, 1024, FPS_SMEM>>>(xyz, centers);
    knn_kernel<<<(Bn * Gn) / 8, 256>>>(xyz, centers, patch);
}

// round 12
// speedup vs baseline: 1.2044x; 1.2044x over previous
#include <cuda_runtime.h>
#include <cuda_bf16.h>

#define Bn 32
#define Nn 8192
#define Gn 256
#define Kn 32
#define CH 1024
#define FULLMASK 0xFFFFFFFFu

// ---------------------------------------------------------------------------
// Kernel 1: farthest point sampling. One block per batch, 1024 threads,
// 8 points/thread in registers. Sub-square distance (reference bit-exact).
// 2 barriers/iter: lane0 stores warp max -> bar -> every warp redundantly
// reduces the 32 warp maxima (redux.sync) -> rare block-max claimant does
// atomicMin on double-buffered s_idx (first-index tie-break == jnp.argmax)
// -> bar -> read winner.
// ---------------------------------------------------------------------------
__global__ __launch_bounds__(1024, 1) void fps_kernel(const float* __restrict__ xyz,
                                                      float* __restrict__ centers)
{
    __shared__ unsigned warpmax[32];
    __shared__ unsigned s_idx[2];

    const int b    = blockIdx.x;
    const int tid  = threadIdx.x;
    const int lane = tid & 31;
    const int wid  = tid >> 5;
    const float* xb = xyz + (size_t)b * Nn * 3;

    // load 8 points = 24 floats = 6 float4 (tid*96 bytes, 16B aligned)
    float px[8], py[8], pz[8], mind[8];
    {
        float c[24];
        const float4* s4 = (const float4*)(xb + tid * 24);
#pragma unroll
        for (int q = 0; q < 6; q++) {
            float4 v = s4[q];
            c[4 * q + 0] = v.x; c[4 * q + 1] = v.y;
            c[4 * q + 2] = v.z; c[4 * q + 3] = v.w;
        }
#pragma unroll
        for (int i = 0; i < 8; i++) {
            px[i] = c[3 * i + 0];
            py[i] = c[3 * i + 1];
            pz[i] = c[3 * i + 2];
            mind[i] = __int_as_float(0x7f800000);  // +inf
        }
    }
    if (tid < 2) s_idx[tid] = 0xFFFFFFFFu;
    __syncthreads();

    int cur = 0;
    for (int g = 0; g < Gn; g++) {
        const int p = g & 1;
        float cx = __ldg(xb + 3 * cur + 0);
        float cy = __ldg(xb + 3 * cur + 1);
        float cz = __ldg(xb + 3 * cur + 2);
        if (tid == 0) {
            float* cp = centers + ((size_t)b * Gn + g) * 3;
            cp[0] = cx; cp[1] = cy; cp[2] = cz;
        }

        float vm = 0.0f;
#pragma unroll
        for (int i = 0; i < 8; i++) {
            // EXACT reference arithmetic: sub then square
            float dx = px[i] - cx, dy = py[i] - cy, dz = pz[i] - cz;
            float d  = dx * dx + dy * dy + dz * dz;
            float m  = fminf(mind[i], d);
            mind[i]  = m;
            vm = fmaxf(vm, m);
        }
        // distances >= 0 -> bit compare == float compare
        unsigned vb   = __float_as_uint(vm);
        unsigned wmax = __reduce_max_sync(FULLMASK, vb);
        if (lane == 0) warpmax[wid] = wmax;
        __syncthreads();                         // bar1: warp maxima visible
        unsigned bm = __reduce_max_sync(FULLMASK, warpmax[lane]);
        if (vb == bm) {                          // ~1 claimant thread
            int j = -1;
#pragma unroll
            for (int i = 7; i >= 0; i--)
                if (__float_as_uint(mind[i]) == bm) j = i;
            if (j >= 0) atomicMin(&s_idx[p], (unsigned)(tid * 8 + j));
        }
        __syncthreads();                         // bar2: claims landed
        cur = (int)s_idx[p];
        if (tid == 0) s_idx[1 - p] = 0xFFFFFFFFu;  // reset for g+1 (pre-bar1 of g+1)
    }
}

// ---------------------------------------------------------------------------
// Kernel 2: exact ordered top-32 per group (round-8 measured-best version).
// One warp per group, slots sorted ascending across lanes by (valbits, idx);
// lane 31 always holds tau. Insert = broadcast + ballot-prefix shift.
// rank == lane.
// ---------------------------------------------------------------------------
__global__ __launch_bounds__(256, 6) void knn_kernel(const float* __restrict__ xyz,
                                                     const float* __restrict__ centers,
                                                     float* __restrict__ patch)
{
    __shared__ float spts[CH * 3];  // 12 KB chunk

    const int b     = blockIdx.x >> 5;        // 32 blocks per batch
    const int gbase = (blockIdx.x & 31) * 8;
    const int wid   = threadIdx.x >> 5;
    const int lane  = threadIdx.x & 31;
    const int g     = gbase + wid;

    const float* cptr = centers + ((size_t)b * Gn + g) * 3;
    float cx = cptr[0], cy = cptr[1], cz = cptr[2];

    // slot: packed (distbits<<32)|idx, sorted ascending by lane
    unsigned long long slot =
        ((unsigned long long)0x7f800000u << 32) | 0xFFFFFFFFull;
    unsigned taub = 0x7f800000u;  // +inf bits

    for (int c = 0; c < Nn / CH; c++) {
        __syncthreads();
        const float4* src4 = (const float4*)(xyz + ((size_t)b * Nn + c * CH) * 3);
        float4* dst4 = (float4*)spts;
        for (int i = threadIdx.x; i < CH * 3 / 4; i += 256) dst4[i] = src4[i];
        __syncthreads();

        for (int s = 0; s < CH / 32; s++) {
            int p = s * 32 + lane;
            float x = spts[3 * p + 0];
            float y = spts[3 * p + 1];
            float z = spts[3 * p + 2];
            // EXACT reference arithmetic
            float dx = cx - x, dy = cy - y, dz = cz - z;
            float key = dx * dx + dy * dy + dz * dz;
            unsigned kb = __float_as_uint(key);
            unsigned gi = (unsigned)(c * CH + p);

            // bit compare == float compare for non-negative floats
            unsigned act = __ballot_sync(FULLMASK, kb < taub);
            while (act) {
                int src = __ffs(act) - 1;
                act &= act - 1;
                unsigned ckb = __shfl_sync(FULLMASK, kb, src);
                unsigned cgi = __shfl_sync(FULLMASK, gi, src);
                if (ckb >= taub) continue;  // uniform: tau dropped below it
                unsigned long long cpk =
                    ((unsigned long long)ckb << 32) | cgi;
                bool gtp = slot > cpk;
                unsigned bal = __ballot_sync(FULLMASK, gtp);
                int pos = __ffs(bal) - 1;  // always >= 0: lane31 slot > cpk
                unsigned long long up = __shfl_up_sync(FULLMASK, slot, 1);
                unsigned long long ns = gtp ? up : slot;
                if (lane == pos) ns = cpk;
                slot = ns;
                taub = __shfl_sync(FULLMASK, (unsigned)(slot >> 32), 31);
            }
        }
    }

    // slots sorted: rank == lane
    unsigned sidx = (unsigned)(slot & 0xFFFFFFFFull);
    const float* pp = xyz + ((size_t)b * Nn + sidx) * 3;
    float* outp = patch + (((size_t)(b * Gn + g)) * Kn + lane) * 3;
    outp[0] = pp[0] - cx;
    outp[1] = pp[1] - cy;
    outp[2] = pp[2] - cz;
}

// ---------------------------------------------------------------------------
extern "C" void kernel_launch(void* const* d_in, const int* in_sizes, int n_in,
                              void* d_out, int out_size)
{
    (void)in_sizes; (void)n_in; (void)out_size;
    const float* xyz = (const float*)d_in[0];
    float* out     = (float*)d_out;
    float* patch   = out;                             // (B, G, K, 3)
    float* centers = out + (size_t)Bn * Gn * Kn * 3;  // (B, G, 3)

    fps_kernel<<<Bn, 1024>>>(xyz, centers);
    knn_kernel<<<(Bn * Gn) / 8, 256>>>(xyz, centers, patch);
}